// round 7
// baseline (speedup 1.0000x reference)
#include <cuda_runtime.h>

// ---------------------------------------------------------------------------
// GCN(D=256) x2 + MLP head, algebraically folded:
//   out = A( A (X Wfold) + c1*1 ) + bc ,  Wfold = W1^T W2^T Wm1^T Wm2^T [256x5]
// A = D^{-1/2}(Adj+I)D^{-1/2}; dinv factored out of edge kernels.
// R7: single stream (no stream/event creation -> no teardown-leak risk);
//     paired-lane edge gather: lanes 2j/2j+1 split each edge's 32B row across
//     one 128B line (1 line-touch/edge instead of 2), even lane -> v4 RED,
//     odd lane -> scalar RED.
// ---------------------------------------------------------------------------

#define Dd 256
#define Hh 128
#define Cc 5
#define Ss 8           // padded row stride (32B rows -> 1 L2 sector)
#define NMAX 100352

__device__ float g_deg[NMAX];        // degree, then dinv in-place
__device__ float g_bufA[NMAX * Ss];  // z' (=dinv*z), then q (=dinv*p)
__device__ float g_bufB[NMAX * Ss];  // edge-sum accumulator (both passes)
__device__ float g_M1[Dd * Cc];      // fold stage-1 intermediate
__device__ float g_WcT[Dd * Cc];     // fold stage-2 intermediate
__device__ float g_W[Dd * Cc];       // folded 256x5 weight
__device__ float g_c1[Cc];
__device__ float g_bc[Cc];

__global__ void init_kernel(int n) {
    int i = blockIdx.x * blockDim.x + threadIdx.x;
    if (i < n) {
        g_deg[i] = 1.0f;  // self-loop contributes 1 to degree
        float4 z = make_float4(0.f, 0.f, 0.f, 0.f);
        ((float4*)g_bufB)[i * 2 + 0] = z;
        ((float4*)g_bufB)[i * 2 + 1] = z;
    }
    if (i < Dd * Cc) { g_M1[i] = 0.f; g_WcT[i] = 0.f; g_W[i] = 0.f; }
}

__global__ void deg_kernel(const int* __restrict__ dst, int E) {
    int t = blockIdx.x * blockDim.x + threadIdx.x;
    int e0 = t * 4;
    if (e0 + 3 < E) {
        int4 d = __ldg((const int4*)(dst + e0));
        atomicAdd(&g_deg[d.x], 1.0f);
        atomicAdd(&g_deg[d.y], 1.0f);
        atomicAdd(&g_deg[d.z], 1.0f);
        atomicAdd(&g_deg[d.w], 1.0f);
    } else {
        for (int e = e0; e < E; ++e) atomicAdd(&g_deg[__ldg(dst + e)], 1.0f);
    }
}

__global__ void dinv_kernel(int n) {
    int i = blockIdx.x * blockDim.x + threadIdx.x;
    if (i < n) g_deg[i] = rsqrtf(g_deg[i]);  // deg >= 1 always
}

// Fold stage: Out[t][c] += sum_{k chunk} A[k*Dd + t] * B[k][c]; bT: B stored [Cc x kdim]
__global__ void stage_kernel(const float* __restrict__ A, const float* __restrict__ B,
                             float* __restrict__ Out, int kdim, int bT) {
    __shared__ float sB[Dd * Cc];
    int tid = threadIdx.x;
    for (int i = tid; i < kdim * Cc; i += blockDim.x) {
        int k = i / Cc, c = i - k * Cc;
        sB[i] = bT ? B[c * kdim + k] : B[i];
    }
    __syncthreads();
    int chunk = kdim / gridDim.x;
    int k0 = blockIdx.x * chunk;
    float acc[Cc] = {};
    for (int k = k0; k < k0 + chunk; ++k) {
        float a = A[k * Dd + tid];
        #pragma unroll
        for (int c = 0; c < Cc; ++c) acc[c] += a * sB[k * Cc + c];
    }
    #pragma unroll
    for (int c = 0; c < Cc; ++c) atomicAdd(&Out[tid * Cc + c], acc[c]);
}

// Bias folds: c1 = b1 @ WcT ; bc = Wm2 (Wm1 b2 + bm1) + bm2
__global__ void bias_kernel(const float* __restrict__ b1, const float* __restrict__ b2,
                            const float* __restrict__ Wm1, const float* __restrict__ bm1,
                            const float* __restrict__ Wm2, const float* __restrict__ bm2) {
    __shared__ float st[Hh];
    int tid = threadIdx.x, w = tid >> 5, lane = tid & 31;  // 8 warps
    for (int i = 0; i < 16; ++i) {
        int h = w * 16 + i;
        float s = 0.f;
        for (int d = lane; d < Dd; d += 32) s += Wm1[h * Dd + d] * b2[d];
        #pragma unroll
        for (int off = 16; off; off >>= 1) s += __shfl_xor_sync(0xFFFFFFFFu, s, off);
        if (lane == 0) st[h] = s + bm1[h];
    }
    __syncthreads();
    if (w < Cc) {
        float s1 = 0.f;
        for (int d = lane; d < Dd; d += 32) s1 += b1[d] * g_WcT[d * Cc + w];
        #pragma unroll
        for (int off = 16; off; off >>= 1) s1 += __shfl_xor_sync(0xFFFFFFFFu, s1, off);
        if (lane == 0) g_c1[w] = s1;
        float s2 = 0.f;
        for (int h = lane; h < Hh; h += 32) s2 += Wm2[w * Hh + h] * st[h];
        #pragma unroll
        for (int off = 16; off; off >>= 1) s2 += __shfl_xor_sync(0xFFFFFFFFu, s2, off);
        if (lane == 0) g_bc[w] = s2 + bm2[w];
    }
}

// z' = dinv * (X @ Wfold): one warp per node, float4 loads of the 1KB row.
__global__ void gemv_kernel(const float* __restrict__ x, int n) {
    __shared__ float sW[Dd * Cc];
    for (int i = threadIdx.x; i < Dd * Cc; i += blockDim.x) sW[i] = g_W[i];
    __syncthreads();
    int gw = (blockIdx.x * blockDim.x + threadIdx.x) >> 5;
    int lane = threadIdx.x & 31;
    if (gw >= n) return;
    const float4* xr = (const float4*)x + (size_t)gw * (Dd / 4);
    float a0 = 0.f, a1 = 0.f, a2 = 0.f, a3 = 0.f, a4 = 0.f;
    #pragma unroll
    for (int it = 0; it < 2; ++it) {
        float4 v = xr[it * 32 + lane];
        const float* w = &sW[(it * 32 + lane) * 4 * Cc];
        a0 += v.x * w[0] + v.y * w[5] + v.z * w[10] + v.w * w[15];
        a1 += v.x * w[1] + v.y * w[6] + v.z * w[11] + v.w * w[16];
        a2 += v.x * w[2] + v.y * w[7] + v.z * w[12] + v.w * w[17];
        a3 += v.x * w[3] + v.y * w[8] + v.z * w[13] + v.w * w[18];
        a4 += v.x * w[4] + v.y * w[9] + v.z * w[14] + v.w * w[19];
    }
    #pragma unroll
    for (int off = 16; off; off >>= 1) {
        a0 += __shfl_xor_sync(0xFFFFFFFFu, a0, off);
        a1 += __shfl_xor_sync(0xFFFFFFFFu, a1, off);
        a2 += __shfl_xor_sync(0xFFFFFFFFu, a2, off);
        a3 += __shfl_xor_sync(0xFFFFFFFFu, a3, off);
        a4 += __shfl_xor_sync(0xFFFFFFFFu, a4, off);
    }
    if (lane == 0) {
        float w = g_deg[gw];  // dinv
        float* o = &g_bufA[(size_t)gw * Ss];
        o[0] = w * a0; o[1] = w * a1; o[2] = w * a2; o[3] = w * a3; o[4] = w * a4;
    }
}

// Paired-lane edge pass: 16 edges per warp; lanes 2j/2j+1 handle edge j.
// Even lane loads row bytes [0,16) and RED.v4s them; odd lane loads bytes
// [16,32) (same 128B line -> wavefront dedup) and REDs the single live float.
__global__ void agg_kernel(const int* __restrict__ src, const int* __restrict__ dst, int E) {
    int gtid = blockIdx.x * blockDim.x + threadIdx.x;
    int warpId = gtid >> 5;
    int lane = threadIdx.x & 31;
    int half = lane & 1;
    int e = warpId * 16 + (lane >> 1);
    if (e >= E) return;
    int s = __ldg(src + e);           // pair lanes load same word: deduped
    int d = __ldg(dst + e);
    float4 v = *(const float4*)&g_bufA[(size_t)s * Ss + half * 4];
    float* vd = &g_bufB[(size_t)d * Ss];
    if (half == 0) {
        unsigned long long gp = __cvta_generic_to_global(vd);
        asm volatile("red.global.add.v4.f32 [%0], {%1, %2, %3, %4};"
                     :: "l"(gp), "f"(v.x), "f"(v.y), "f"(v.z), "f"(v.w) : "memory");
    } else {
        atomicAdd(vd + 4, v.x);       // row float 4
    }
}

// After pass 1: p = dinv*(S1 + z') + c1 ;  q = dinv*p -> bufA; reset bufB.
__global__ void fin1_kernel(int n) {
    int i = blockIdx.x * blockDim.x + threadIdx.x;
    if (i >= n) return;
    float w = g_deg[i];
    #pragma unroll
    for (int c = 0; c < Cc; ++c) {
        float pp = w * (g_bufB[i * Ss + c] + g_bufA[i * Ss + c]) + g_c1[c];
        g_bufA[i * Ss + c] = w * pp;
        g_bufB[i * Ss + c] = 0.f;
    }
}

// After pass 2: out = dinv*(S2 + q) + bc
__global__ void fin2_kernel(float* __restrict__ out, int n) {
    int i = blockIdx.x * blockDim.x + threadIdx.x;
    if (i >= n) return;
    float w = g_deg[i];
    #pragma unroll
    for (int c = 0; c < Cc; ++c) {
        out[i * Cc + c] = w * (g_bufB[i * Ss + c] + g_bufA[i * Ss + c]) + g_bc[c];
    }
}

extern "C" void kernel_launch(void* const* d_in, const int* in_sizes, int n_in,
                              void* d_out, int out_size) {
    const float* x   = (const float*)d_in[0];
    const int*   ei  = (const int*)d_in[1];
    const float* W1  = (const float*)d_in[2];
    const float* b1  = (const float*)d_in[3];
    const float* W2  = (const float*)d_in[4];
    const float* b2  = (const float*)d_in[5];
    const float* Wm1 = (const float*)d_in[6];
    const float* bm1 = (const float*)d_in[7];
    const float* Wm2 = (const float*)d_in[8];
    const float* bm2 = (const float*)d_in[9];
    float* out = (float*)d_out;

    int n = in_sizes[0] / Dd;
    int E = in_sizes[1] / 2;
    const int* src = ei;
    const int* dst = ei + E;

    int nb  = (n + 255) / 256;
    int eb4 = ((E + 3) / 4 + 255) / 256;           // 4 edges/thread (deg)
    long long athreads = (long long)((E + 15) / 16) * 32;  // paired-lane agg
    int ab  = (int)((athreads + 255) / 256);
    int gb  = (n * 32 + 255) / 256;                // warp-per-node GEMV

    float* pM1  = nullptr; cudaGetSymbolAddress((void**)&pM1,  g_M1);
    float* pWcT = nullptr; cudaGetSymbolAddress((void**)&pWcT, g_WcT);
    float* pW   = nullptr; cudaGetSymbolAddress((void**)&pW,   g_W);

    init_kernel<<<nb, 256>>>(n);
    deg_kernel<<<eb4, 256>>>(dst, E);
    dinv_kernel<<<nb, 256>>>(n);
    // fold: M1 = Wm1^T Wm2^T ; WcT = W2^T M1 ; Wfold = W1^T WcT
    stage_kernel<<<16, 256>>>(Wm1, Wm2, pM1, Hh, 1);
    stage_kernel<<<32, 256>>>(W2, pM1, pWcT, Dd, 0);
    stage_kernel<<<32, 256>>>(W1, pWcT, pW, Dd, 0);
    bias_kernel<<<1, 256>>>(b1, b2, Wm1, bm1, Wm2, bm2);
    gemv_kernel<<<gb, 256>>>(x, n);
    agg_kernel<<<ab, 256>>>(src, dst, E);   // pass 1
    fin1_kernel<<<nb, 256>>>(n);
    agg_kernel<<<ab, 256>>>(src, dst, E);   // pass 2
    fin2_kernel<<<nb, 256>>>(out, n);
}

// round 8
// speedup vs baseline: 1.0463x; 1.0463x over previous
#include <cuda_runtime.h>

// ---------------------------------------------------------------------------
// GCN(D=256) x2 + MLP head, algebraically folded:
//   out = A( A (X Wfold) + c1*1 ) + bc ,  Wfold = W1^T W2^T Wm1^T Wm2^T [256x5]
// A = D^{-1/2}(Adj+I)D^{-1/2}; dinv factored out of edge kernels.
// R8: whole weight-fold (3 chained 5-col GEMMs + both bias folds) fused into
//     ONE 16-block kernel with spin grid-barriers (no atomics, block-owned
//     output rows); dinv kernel deleted (rsqrtf inline); fin1/fin2 vectorized.
//     Edge engine unchanged from R5 (best measured: 2 edges/thread, v4 RED).
// ---------------------------------------------------------------------------

#define Dd 256
#define Hh 128
#define Cc 5
#define Ss 8           // padded row stride (32B rows -> 1 L2 sector)
#define NMAX 100352
#define FOLD_BLOCKS 16

__device__ float g_deg[NMAX];        // raw degree (self-loop included)
__device__ float g_bufA[NMAX * Ss];  // z' (=dinv*z), then q (=dinv*p)
__device__ float g_bufB[NMAX * Ss];  // edge-sum accumulator (both passes)
__device__ float g_M1[Dd * Cc];      // fold stage-1 intermediate
__device__ float g_WcT[Dd * Cc];     // fold stage-2 intermediate
__device__ float g_W[Dd * Cc];       // folded 256x5 weight
__device__ float g_c1[Cc];
__device__ float g_bc[Cc];
__device__ unsigned g_bar;           // fold grid-barrier counter (reset per launch)

__global__ void init_kernel(int n) {
    int i = blockIdx.x * blockDim.x + threadIdx.x;
    if (i < n) {
        g_deg[i] = 1.0f;  // self-loop contributes 1 to degree
        float4 z = make_float4(0.f, 0.f, 0.f, 0.f);
        ((float4*)g_bufB)[i * 2 + 0] = z;
        ((float4*)g_bufB)[i * 2 + 1] = z;
    }
    if (i == 0) g_bar = 0u;
}

__global__ void deg_kernel(const int* __restrict__ dst, int E) {
    int t = blockIdx.x * blockDim.x + threadIdx.x;
    int e0 = t * 4;
    if (e0 + 3 < E) {
        int4 d = __ldg((const int4*)(dst + e0));
        atomicAdd(&g_deg[d.x], 1.0f);
        atomicAdd(&g_deg[d.y], 1.0f);
        atomicAdd(&g_deg[d.z], 1.0f);
        atomicAdd(&g_deg[d.w], 1.0f);
    } else {
        for (int e = e0; e < E; ++e) atomicAdd(&g_deg[__ldg(dst + e)], 1.0f);
    }
}

// Spin grid barrier for the fold kernel (FOLD_BLOCKS co-resident blocks).
__device__ __forceinline__ void fold_gbar(unsigned target) {
    __syncthreads();
    if (threadIdx.x == 0) {
        asm volatile("red.release.gpu.global.add.u32 [%0], 1;"
                     :: "l"(&g_bar) : "memory");
        unsigned v;
        do {
            asm volatile("ld.acquire.gpu.global.u32 %0, [%1];"
                         : "=r"(v) : "l"(&g_bar) : "memory");
        } while (v < target);
    }
    __syncthreads();
}

// Fused fold: M1 = Wm1^T Wm2^T ; WcT = W2^T M1 ; Wfold = W1^T WcT ; biases.
// 16 blocks x 256 threads. Each block owns 16 output rows per phase; within a
// block, thread t = (part<<4)|rloc: rloc picks the row, part splits the k-dim;
// partials reduced through shared memory. Cross-block intermediates are
// first-touch reads after the barrier (no stale L1).
__global__ void fold_kernel(const float* __restrict__ W1, const float* __restrict__ b1,
                            const float* __restrict__ W2, const float* __restrict__ b2,
                            const float* __restrict__ Wm1, const float* __restrict__ bm1,
                            const float* __restrict__ Wm2, const float* __restrict__ bm2) {
    __shared__ float red[256 * Cc];
    __shared__ float st[Hh];
    int t = threadIdx.x;
    int rloc = t & 15, part = t >> 4;      // 16 rows/block, 16 k-parts
    int r = blockIdx.x * 16 + rloc;

    // Phase A: M1[r][c] = sum_h Wm1[h,r] * Wm2[c,h]   (h = 128)
    {
        float acc[Cc] = {};
        for (int h = part * 8; h < part * 8 + 8; ++h) {
            float a = Wm1[h * Dd + r];
            #pragma unroll
            for (int c = 0; c < Cc; ++c) acc[c] += a * Wm2[c * Hh + h];
        }
        #pragma unroll
        for (int c = 0; c < Cc; ++c) red[t * Cc + c] = acc[c];
        __syncthreads();
        if (part == 0) {
            float s[Cc] = {};
            for (int p = 0; p < 16; ++p)
                #pragma unroll
                for (int c = 0; c < Cc; ++c) s[c] += red[(p * 16 + rloc) * Cc + c];
            #pragma unroll
            for (int c = 0; c < Cc; ++c) g_M1[r * Cc + c] = s[c];
        }
    }
    fold_gbar(FOLD_BLOCKS);

    // Phase B: WcT[r][c] = sum_k W2[k,r] * M1[k][c]   (k = 256)
    {
        float acc[Cc] = {};
        for (int k = part * 16; k < part * 16 + 16; ++k) {
            float a = W2[k * Dd + r];
            #pragma unroll
            for (int c = 0; c < Cc; ++c) acc[c] += a * g_M1[k * Cc + c];
        }
        #pragma unroll
        for (int c = 0; c < Cc; ++c) red[t * Cc + c] = acc[c];
        __syncthreads();
        if (part == 0) {
            float s[Cc] = {};
            for (int p = 0; p < 16; ++p)
                #pragma unroll
                for (int c = 0; c < Cc; ++c) s[c] += red[(p * 16 + rloc) * Cc + c];
            #pragma unroll
            for (int c = 0; c < Cc; ++c) g_WcT[r * Cc + c] = s[c];
        }
    }
    fold_gbar(2 * FOLD_BLOCKS);

    // Phase C: Wfold[r][c] = sum_k W1[k,r] * WcT[k][c]   (k = 256)
    {
        float acc[Cc] = {};
        for (int k = part * 16; k < part * 16 + 16; ++k) {
            float a = W1[k * Dd + r];
            #pragma unroll
            for (int c = 0; c < Cc; ++c) acc[c] += a * g_WcT[k * Cc + c];
        }
        #pragma unroll
        for (int c = 0; c < Cc; ++c) red[t * Cc + c] = acc[c];
        __syncthreads();
        if (part == 0) {
            float s[Cc] = {};
            for (int p = 0; p < 16; ++p)
                #pragma unroll
                for (int c = 0; c < Cc; ++c) s[c] += red[(p * 16 + rloc) * Cc + c];
            #pragma unroll
            for (int c = 0; c < Cc; ++c) g_W[r * Cc + c] = s[c];
        }
    }

    // Phase D (block 0 only): c1 = b1 @ WcT ; bc = Wm2 (Wm1 b2 + bm1) + bm2
    if (blockIdx.x == 0) {
        __syncthreads();
        int w = t >> 5, lane = t & 31;     // 8 warps
        for (int i = 0; i < 16; ++i) {
            int h = w * 16 + i;
            float s = 0.f;
            for (int d = lane; d < Dd; d += 32) s += Wm1[h * Dd + d] * b2[d];
            #pragma unroll
            for (int off = 16; off; off >>= 1) s += __shfl_xor_sync(0xFFFFFFFFu, s, off);
            if (lane == 0) st[h] = s + bm1[h];
        }
        __syncthreads();
        if (w < Cc) {
            float s1 = 0.f;
            for (int d = lane; d < Dd; d += 32) s1 += b1[d] * g_WcT[d * Cc + w];
            #pragma unroll
            for (int off = 16; off; off >>= 1) s1 += __shfl_xor_sync(0xFFFFFFFFu, s1, off);
            if (lane == 0) g_c1[w] = s1;
            float s2 = 0.f;
            for (int h = lane; h < Hh; h += 32) s2 += Wm2[w * Hh + h] * st[h];
            #pragma unroll
            for (int off = 16; off; off >>= 1) s2 += __shfl_xor_sync(0xFFFFFFFFu, s2, off);
            if (lane == 0) g_bc[w] = s2 + bm2[w];
        }
    }
}

// z' = dinv * (X @ Wfold): one warp per node, float4 loads of the 1KB row.
__global__ void gemv_kernel(const float* __restrict__ x, int n) {
    __shared__ float sW[Dd * Cc];
    for (int i = threadIdx.x; i < Dd * Cc; i += blockDim.x) sW[i] = g_W[i];
    __syncthreads();
    int gw = (blockIdx.x * blockDim.x + threadIdx.x) >> 5;
    int lane = threadIdx.x & 31;
    if (gw >= n) return;
    const float4* xr = (const float4*)x + (size_t)gw * (Dd / 4);
    float a0 = 0.f, a1 = 0.f, a2 = 0.f, a3 = 0.f, a4 = 0.f;
    #pragma unroll
    for (int it = 0; it < 2; ++it) {
        float4 v = xr[it * 32 + lane];
        const float* w = &sW[(it * 32 + lane) * 4 * Cc];
        a0 += v.x * w[0] + v.y * w[5] + v.z * w[10] + v.w * w[15];
        a1 += v.x * w[1] + v.y * w[6] + v.z * w[11] + v.w * w[16];
        a2 += v.x * w[2] + v.y * w[7] + v.z * w[12] + v.w * w[17];
        a3 += v.x * w[3] + v.y * w[8] + v.z * w[13] + v.w * w[18];
        a4 += v.x * w[4] + v.y * w[9] + v.z * w[14] + v.w * w[19];
    }
    #pragma unroll
    for (int off = 16; off; off >>= 1) {
        a0 += __shfl_xor_sync(0xFFFFFFFFu, a0, off);
        a1 += __shfl_xor_sync(0xFFFFFFFFu, a1, off);
        a2 += __shfl_xor_sync(0xFFFFFFFFu, a2, off);
        a3 += __shfl_xor_sync(0xFFFFFFFFu, a3, off);
        a4 += __shfl_xor_sync(0xFFFFFFFFu, a4, off);
    }
    if (lane == 0) {
        float w = rsqrtf(g_deg[gw]);   // dinv inline (deg >= 1 always)
        float* o = &g_bufA[(size_t)gw * Ss];
        o[0] = w * a0; o[1] = w * a1; o[2] = w * a2; o[3] = w * a3; o[4] = w * a4;
    }
}

__device__ __forceinline__ void red_row(int d, float4 a, float a4) {
    float* vd = &g_bufB[(size_t)d * Ss];
    unsigned long long gp = __cvta_generic_to_global(vd);
    asm volatile("red.global.add.v4.f32 [%0], {%1, %2, %3, %4};"
                 :: "l"(gp), "f"(a.x), "f"(a.y), "f"(a.z), "f"(a.w) : "memory");
    atomicAdd(vd + 4, a4);
}

// Edge pass: bufB[dst] += bufA[src], 2 edges per thread (R5 form, best measured).
__global__ void agg_kernel(const int* __restrict__ src, const int* __restrict__ dst, int E) {
    int t = blockIdx.x * blockDim.x + threadIdx.x;
    int e0 = t * 2;
    if (e0 + 1 < E) {
        int2 s = __ldg((const int2*)(src + e0));
        int2 d = __ldg((const int2*)(dst + e0));
        const float* vs0 = &g_bufA[(size_t)s.x * Ss];
        const float* vs1 = &g_bufA[(size_t)s.y * Ss];
        float4 a = *(const float4*)vs0;
        float4 b = *(const float4*)vs1;
        float a4 = vs0[4];
        float b4 = vs1[4];
        red_row(d.x, a, a4);
        red_row(d.y, b, b4);
    } else if (e0 < E) {
        int s = __ldg(src + e0);
        int d = __ldg(dst + e0);
        const float* vs = &g_bufA[(size_t)s * Ss];
        red_row(d, *(const float4*)vs, vs[4]);
    }
}

// After pass 1: p = dinv*(S1 + z') + c1 ;  q = dinv*p -> bufA; reset bufB.
__global__ void fin1_kernel(int n) {
    int i = blockIdx.x * blockDim.x + threadIdx.x;
    if (i >= n) return;
    float w = rsqrtf(g_deg[i]);
    float4 sB = *(const float4*)&g_bufB[i * Ss];
    float  sB4 = g_bufB[i * Ss + 4];
    float4 zA = *(const float4*)&g_bufA[i * Ss];
    float  zA4 = g_bufA[i * Ss + 4];
    float4 q;
    q.x = w * (w * (sB.x + zA.x) + g_c1[0]);
    q.y = w * (w * (sB.y + zA.y) + g_c1[1]);
    q.z = w * (w * (sB.z + zA.z) + g_c1[2]);
    q.w = w * (w * (sB.w + zA.w) + g_c1[3]);
    float q4 = w * (w * (sB4 + zA4) + g_c1[4]);
    *(float4*)&g_bufA[i * Ss] = q;
    g_bufA[i * Ss + 4] = q4;
    *(float4*)&g_bufB[i * Ss] = make_float4(0.f, 0.f, 0.f, 0.f);
    g_bufB[i * Ss + 4] = 0.f;
}

// After pass 2: out = dinv*(S2 + q) + bc
__global__ void fin2_kernel(float* __restrict__ out, int n) {
    int i = blockIdx.x * blockDim.x + threadIdx.x;
    if (i >= n) return;
    float w = rsqrtf(g_deg[i]);
    float4 sB = *(const float4*)&g_bufB[i * Ss];
    float  sB4 = g_bufB[i * Ss + 4];
    float4 qA = *(const float4*)&g_bufA[i * Ss];
    float  qA4 = g_bufA[i * Ss + 4];
    float* o = out + (size_t)i * Cc;
    o[0] = w * (sB.x + qA.x) + g_bc[0];
    o[1] = w * (sB.y + qA.y) + g_bc[1];
    o[2] = w * (sB.z + qA.z) + g_bc[2];
    o[3] = w * (sB.w + qA.w) + g_bc[3];
    o[4] = w * (sB4 + qA4) + g_bc[4];
}

extern "C" void kernel_launch(void* const* d_in, const int* in_sizes, int n_in,
                              void* d_out, int out_size) {
    const float* x   = (const float*)d_in[0];
    const int*   ei  = (const int*)d_in[1];
    const float* W1  = (const float*)d_in[2];
    const float* b1  = (const float*)d_in[3];
    const float* W2  = (const float*)d_in[4];
    const float* b2  = (const float*)d_in[5];
    const float* Wm1 = (const float*)d_in[6];
    const float* bm1 = (const float*)d_in[7];
    const float* Wm2 = (const float*)d_in[8];
    const float* bm2 = (const float*)d_in[9];
    float* out = (float*)d_out;

    int n = in_sizes[0] / Dd;
    int E = in_sizes[1] / 2;
    const int* src = ei;
    const int* dst = ei + E;

    int nb  = (n + 255) / 256;
    int eb4 = ((E + 3) / 4 + 255) / 256;   // 4 edges/thread (deg)
    int eb2 = ((E + 1) / 2 + 255) / 256;   // 2 edges/thread (agg)
    int gb  = (n * 32 + 255) / 256;        // warp-per-node GEMV

    init_kernel<<<nb, 256>>>(n);
    deg_kernel<<<eb4, 256>>>(dst, E);
    fold_kernel<<<FOLD_BLOCKS, 256>>>(W1, b1, W2, b2, Wm1, bm1, Wm2, bm2);
    gemv_kernel<<<gb, 256>>>(x, n);
    agg_kernel<<<eb2, 256>>>(src, dst, E);   // pass 1
    fin1_kernel<<<nb, 256>>>(n);
    agg_kernel<<<eb2, 256>>>(src, dst, E);   // pass 2
    fin2_kernel<<<nb, 256>>>(out, n);
}

// round 9
// speedup vs baseline: 1.0992x; 1.0506x over previous
#include <cuda_runtime.h>

// ---------------------------------------------------------------------------
// GCN(D=256) x2 + MLP head, algebraically folded:
//   out = A( A (X Wfold) + c1*1 ) + bc ,  Wfold = W1^T W2^T Wm1^T Wm2^T [256x5]
// A = D^{-1/2}(Adj+I)D^{-1/2}; dinv factored out of edge kernels.
// R9: gemv rewritten as grid-stride warp-per-node with the 40 per-lane folded
//     weights preloaded into REGISTERS (was: 40 scalar LDS/thread with 4-way
//     bank conflicts -> 76.7% L1 -> 37.8us). Weights stored channel-major by
//     the fused fold kernel. Rest unchanged from R8.
// ---------------------------------------------------------------------------

#define Dd 256
#define Hh 128
#define Cc 5
#define Ss 8           // padded row stride (32B rows -> 1 L2 sector)
#define NMAX 100352
#define FOLD_BLOCKS 16
#define GEMV_BLOCKS 1184

__device__ float g_deg[NMAX];        // raw degree (self-loop included)
__device__ float g_bufA[NMAX * Ss];  // z' (=dinv*z), then q (=dinv*p)
__device__ float g_bufB[NMAX * Ss];  // edge-sum accumulator (both passes)
__device__ float g_M1[Dd * Cc];      // fold stage-1 intermediate
__device__ float g_WcT[Dd * Cc];     // fold stage-2 intermediate
__device__ float g_Wc[Cc * Dd];      // folded weight, channel-major [c][k]
__device__ float g_c1[Cc];
__device__ float g_bc[Cc];
__device__ unsigned g_bar;           // fold grid-barrier counter (reset per launch)

__global__ void init_kernel(int n) {
    int i = blockIdx.x * blockDim.x + threadIdx.x;
    if (i < n) {
        g_deg[i] = 1.0f;  // self-loop contributes 1 to degree
        float4 z = make_float4(0.f, 0.f, 0.f, 0.f);
        ((float4*)g_bufB)[i * 2 + 0] = z;
        ((float4*)g_bufB)[i * 2 + 1] = z;
    }
    if (i == 0) g_bar = 0u;
}

__global__ void deg_kernel(const int* __restrict__ dst, int E) {
    int t = blockIdx.x * blockDim.x + threadIdx.x;
    int e0 = t * 4;
    if (e0 + 3 < E) {
        int4 d = __ldg((const int4*)(dst + e0));
        atomicAdd(&g_deg[d.x], 1.0f);
        atomicAdd(&g_deg[d.y], 1.0f);
        atomicAdd(&g_deg[d.z], 1.0f);
        atomicAdd(&g_deg[d.w], 1.0f);
    } else {
        for (int e = e0; e < E; ++e) atomicAdd(&g_deg[__ldg(dst + e)], 1.0f);
    }
}

// Spin grid barrier for the fold kernel (FOLD_BLOCKS co-resident blocks).
__device__ __forceinline__ void fold_gbar(unsigned target) {
    __syncthreads();
    if (threadIdx.x == 0) {
        asm volatile("red.release.gpu.global.add.u32 [%0], 1;"
                     :: "l"(&g_bar) : "memory");
        unsigned v;
        do {
            asm volatile("ld.acquire.gpu.global.u32 %0, [%1];"
                         : "=r"(v) : "l"(&g_bar) : "memory");
        } while (v < target);
    }
    __syncthreads();
}

// Fused fold: M1 = Wm1^T Wm2^T ; WcT = W2^T M1 ; Wfold = W1^T WcT ; biases.
// 16 blocks x 256 threads; block-owned output rows; spin grid barriers.
__global__ void fold_kernel(const float* __restrict__ W1, const float* __restrict__ b1,
                            const float* __restrict__ W2, const float* __restrict__ b2,
                            const float* __restrict__ Wm1, const float* __restrict__ bm1,
                            const float* __restrict__ Wm2, const float* __restrict__ bm2) {
    __shared__ float red[256 * Cc];
    __shared__ float st[Hh];
    int t = threadIdx.x;
    int rloc = t & 15, part = t >> 4;      // 16 rows/block, 16 k-parts
    int r = blockIdx.x * 16 + rloc;

    // Phase A: M1[r][c] = sum_h Wm1[h,r] * Wm2[c,h]   (h = 128)
    {
        float acc[Cc] = {};
        for (int h = part * 8; h < part * 8 + 8; ++h) {
            float a = Wm1[h * Dd + r];
            #pragma unroll
            for (int c = 0; c < Cc; ++c) acc[c] += a * Wm2[c * Hh + h];
        }
        #pragma unroll
        for (int c = 0; c < Cc; ++c) red[t * Cc + c] = acc[c];
        __syncthreads();
        if (part == 0) {
            float s[Cc] = {};
            for (int p = 0; p < 16; ++p)
                #pragma unroll
                for (int c = 0; c < Cc; ++c) s[c] += red[(p * 16 + rloc) * Cc + c];
            #pragma unroll
            for (int c = 0; c < Cc; ++c) g_M1[r * Cc + c] = s[c];
        }
    }
    fold_gbar(FOLD_BLOCKS);

    // Phase B: WcT[r][c] = sum_k W2[k,r] * M1[k][c]   (k = 256)
    {
        float acc[Cc] = {};
        for (int k = part * 16; k < part * 16 + 16; ++k) {
            float a = W2[k * Dd + r];
            #pragma unroll
            for (int c = 0; c < Cc; ++c) acc[c] += a * g_M1[k * Cc + c];
        }
        #pragma unroll
        for (int c = 0; c < Cc; ++c) red[t * Cc + c] = acc[c];
        __syncthreads();
        if (part == 0) {
            float s[Cc] = {};
            for (int p = 0; p < 16; ++p)
                #pragma unroll
                for (int c = 0; c < Cc; ++c) s[c] += red[(p * 16 + rloc) * Cc + c];
            #pragma unroll
            for (int c = 0; c < Cc; ++c) g_WcT[r * Cc + c] = s[c];
        }
    }
    fold_gbar(2 * FOLD_BLOCKS);

    // Phase C: Wfold[r][c] = sum_k W1[k,r] * WcT[k][c]  -> channel-major g_Wc
    {
        float acc[Cc] = {};
        for (int k = part * 16; k < part * 16 + 16; ++k) {
            float a = W1[k * Dd + r];
            #pragma unroll
            for (int c = 0; c < Cc; ++c) acc[c] += a * g_WcT[k * Cc + c];
        }
        #pragma unroll
        for (int c = 0; c < Cc; ++c) red[t * Cc + c] = acc[c];
        __syncthreads();
        if (part == 0) {
            float s[Cc] = {};
            for (int p = 0; p < 16; ++p)
                #pragma unroll
                for (int c = 0; c < Cc; ++c) s[c] += red[(p * 16 + rloc) * Cc + c];
            #pragma unroll
            for (int c = 0; c < Cc; ++c) g_Wc[c * Dd + r] = s[c];
        }
    }

    // Phase D (block 0 only): c1 = b1 @ WcT ; bc = Wm2 (Wm1 b2 + bm1) + bm2
    if (blockIdx.x == 0) {
        __syncthreads();
        int w = t >> 5, lane = t & 31;     // 8 warps
        for (int i = 0; i < 16; ++i) {
            int h = w * 16 + i;
            float s = 0.f;
            for (int d = lane; d < Dd; d += 32) s += Wm1[h * Dd + d] * b2[d];
            #pragma unroll
            for (int off = 16; off; off >>= 1) s += __shfl_xor_sync(0xFFFFFFFFu, s, off);
            if (lane == 0) st[h] = s + bm1[h];
        }
        __syncthreads();
        if (w < Cc) {
            float s1 = 0.f;
            for (int d = lane; d < Dd; d += 32) s1 += b1[d] * g_WcT[d * Cc + w];
            #pragma unroll
            for (int off = 16; off; off >>= 1) s1 += __shfl_xor_sync(0xFFFFFFFFu, s1, off);
            if (lane == 0) g_c1[w] = s1;
            float s2 = 0.f;
            for (int h = lane; h < Hh; h += 32) s2 += Wm2[w * Hh + h] * st[h];
            #pragma unroll
            for (int off = 16; off; off >>= 1) s2 += __shfl_xor_sync(0xFFFFFFFFu, s2, off);
            if (lane == 0) g_bc[w] = s2 + bm2[w];
        }
    }
}

// z' = dinv * (X @ Wfold): grid-stride warp-per-node; the 40 per-lane weight
// values live in registers (loaded once per thread; no LDS in the hot loop).
__global__ void gemv_kernel(const float* __restrict__ x, int n) {
    int lane = threadIdx.x & 31;
    // wreg[it][j][c]: weight for x-element (it*32+lane)*4+j, channel c
    float wreg[2][4][Cc];
    #pragma unroll
    for (int it = 0; it < 2; ++it) {
        int base = (it * 32 + lane) * 4;
        #pragma unroll
        for (int j = 0; j < 4; ++j)
            #pragma unroll
            for (int c = 0; c < Cc; ++c)
                wreg[it][j][c] = __ldg(&g_Wc[c * Dd + base + j]);
    }
    int nwarps = (GEMV_BLOCKS * 256) >> 5;
    int gw0 = (blockIdx.x * blockDim.x + threadIdx.x) >> 5;
    for (int gw = gw0; gw < n; gw += nwarps) {
        const float4* xr = (const float4*)x + (size_t)gw * (Dd / 4);
        float a0 = 0.f, a1 = 0.f, a2 = 0.f, a3 = 0.f, a4 = 0.f;
        #pragma unroll
        for (int it = 0; it < 2; ++it) {
            float4 v = xr[it * 32 + lane];
            a0 += v.x*wreg[it][0][0] + v.y*wreg[it][1][0] + v.z*wreg[it][2][0] + v.w*wreg[it][3][0];
            a1 += v.x*wreg[it][0][1] + v.y*wreg[it][1][1] + v.z*wreg[it][2][1] + v.w*wreg[it][3][1];
            a2 += v.x*wreg[it][0][2] + v.y*wreg[it][1][2] + v.z*wreg[it][2][2] + v.w*wreg[it][3][2];
            a3 += v.x*wreg[it][0][3] + v.y*wreg[it][1][3] + v.z*wreg[it][2][3] + v.w*wreg[it][3][3];
            a4 += v.x*wreg[it][0][4] + v.y*wreg[it][1][4] + v.z*wreg[it][2][4] + v.w*wreg[it][3][4];
        }
        #pragma unroll
        for (int off = 16; off; off >>= 1) {
            a0 += __shfl_xor_sync(0xFFFFFFFFu, a0, off);
            a1 += __shfl_xor_sync(0xFFFFFFFFu, a1, off);
            a2 += __shfl_xor_sync(0xFFFFFFFFu, a2, off);
            a3 += __shfl_xor_sync(0xFFFFFFFFu, a3, off);
            a4 += __shfl_xor_sync(0xFFFFFFFFu, a4, off);
        }
        if (lane == 0) {
            float w = rsqrtf(g_deg[gw]);   // dinv inline (deg >= 1 always)
            float* o = &g_bufA[(size_t)gw * Ss];
            o[0] = w * a0; o[1] = w * a1; o[2] = w * a2; o[3] = w * a3; o[4] = w * a4;
        }
    }
}

__device__ __forceinline__ void red_row(int d, float4 a, float a4) {
    float* vd = &g_bufB[(size_t)d * Ss];
    unsigned long long gp = __cvta_generic_to_global(vd);
    asm volatile("red.global.add.v4.f32 [%0], {%1, %2, %3, %4};"
                 :: "l"(gp), "f"(a.x), "f"(a.y), "f"(a.z), "f"(a.w) : "memory");
    atomicAdd(vd + 4, a4);
}

// Edge pass: bufB[dst] += bufA[src], 2 edges per thread (R5 form, best measured).
__global__ void agg_kernel(const int* __restrict__ src, const int* __restrict__ dst, int E) {
    int t = blockIdx.x * blockDim.x + threadIdx.x;
    int e0 = t * 2;
    if (e0 + 1 < E) {
        int2 s = __ldg((const int2*)(src + e0));
        int2 d = __ldg((const int2*)(dst + e0));
        const float* vs0 = &g_bufA[(size_t)s.x * Ss];
        const float* vs1 = &g_bufA[(size_t)s.y * Ss];
        float4 a = *(const float4*)vs0;
        float4 b = *(const float4*)vs1;
        float a4 = vs0[4];
        float b4 = vs1[4];
        red_row(d.x, a, a4);
        red_row(d.y, b, b4);
    } else if (e0 < E) {
        int s = __ldg(src + e0);
        int d = __ldg(dst + e0);
        const float* vs = &g_bufA[(size_t)s * Ss];
        red_row(d, *(const float4*)vs, vs[4]);
    }
}

// After pass 1: p = dinv*(S1 + z') + c1 ;  q = dinv*p -> bufA; reset bufB.
__global__ void fin1_kernel(int n) {
    int i = blockIdx.x * blockDim.x + threadIdx.x;
    if (i >= n) return;
    float w = rsqrtf(g_deg[i]);
    float4 sB = *(const float4*)&g_bufB[i * Ss];
    float  sB4 = g_bufB[i * Ss + 4];
    float4 zA = *(const float4*)&g_bufA[i * Ss];
    float  zA4 = g_bufA[i * Ss + 4];
    float4 q;
    q.x = w * (w * (sB.x + zA.x) + g_c1[0]);
    q.y = w * (w * (sB.y + zA.y) + g_c1[1]);
    q.z = w * (w * (sB.z + zA.z) + g_c1[2]);
    q.w = w * (w * (sB.w + zA.w) + g_c1[3]);
    float q4 = w * (w * (sB4 + zA4) + g_c1[4]);
    *(float4*)&g_bufA[i * Ss] = q;
    g_bufA[i * Ss + 4] = q4;
    *(float4*)&g_bufB[i * Ss] = make_float4(0.f, 0.f, 0.f, 0.f);
    g_bufB[i * Ss + 4] = 0.f;
}

// After pass 2: out = dinv*(S2 + q) + bc
__global__ void fin2_kernel(float* __restrict__ out, int n) {
    int i = blockIdx.x * blockDim.x + threadIdx.x;
    if (i >= n) return;
    float w = rsqrtf(g_deg[i]);
    float4 sB = *(const float4*)&g_bufB[i * Ss];
    float  sB4 = g_bufB[i * Ss + 4];
    float4 qA = *(const float4*)&g_bufA[i * Ss];
    float  qA4 = g_bufA[i * Ss + 4];
    float* o = out + (size_t)i * Cc;
    o[0] = w * (sB.x + qA.x) + g_bc[0];
    o[1] = w * (sB.y + qA.y) + g_bc[1];
    o[2] = w * (sB.z + qA.z) + g_bc[2];
    o[3] = w * (sB.w + qA.w) + g_bc[3];
    o[4] = w * (sB4 + qA4) + g_bc[4];
}

extern "C" void kernel_launch(void* const* d_in, const int* in_sizes, int n_in,
                              void* d_out, int out_size) {
    const float* x   = (const float*)d_in[0];
    const int*   ei  = (const int*)d_in[1];
    const float* W1  = (const float*)d_in[2];
    const float* b1  = (const float*)d_in[3];
    const float* W2  = (const float*)d_in[4];
    const float* b2  = (const float*)d_in[5];
    const float* Wm1 = (const float*)d_in[6];
    const float* bm1 = (const float*)d_in[7];
    const float* Wm2 = (const float*)d_in[8];
    const float* bm2 = (const float*)d_in[9];
    float* out = (float*)d_out;

    int n = in_sizes[0] / Dd;
    int E = in_sizes[1] / 2;
    const int* src = ei;
    const int* dst = ei + E;

    int nb  = (n + 255) / 256;
    int eb4 = ((E + 3) / 4 + 255) / 256;   // 4 edges/thread (deg)
    int eb2 = ((E + 1) / 2 + 255) / 256;   // 2 edges/thread (agg)

    init_kernel<<<nb, 256>>>(n);
    deg_kernel<<<eb4, 256>>>(dst, E);
    fold_kernel<<<FOLD_BLOCKS, 256>>>(W1, b1, W2, b2, Wm1, bm1, Wm2, bm2);
    gemv_kernel<<<GEMV_BLOCKS, 256>>>(x, n);
    agg_kernel<<<eb2, 256>>>(src, dst, E);   // pass 1
    fin1_kernel<<<nb, 256>>>(n);
    agg_kernel<<<eb2, 256>>>(src, dst, E);   // pass 2
    fin2_kernel<<<nb, 256>>>(out, n);
}